// round 3
// baseline (speedup 1.0000x reference)
#include <cuda_runtime.h>
#include <math.h>

#define NH 16
#define NB 2
#define NT 2048
#define NC 1024
#define ND 64
#define MTOT (NB*NT)   // 4096

// Scratch (allocation-free rule: __device__ globals). 16 MB each.
__device__ float g_Q[(size_t)NB*NH*NT*ND];
__device__ float g_K[(size_t)NB*NH*NT*ND];
__device__ float g_V[(size_t)NB*NH*NT*ND];
__device__ float g_Y[(size_t)MTOT*NC];

// ---------------------------------------------------------------------------
// Kernel 1: qkv = x @ W_attn^T, scattered into Q/K/V as [B,H,T,d].
// A = x [M=4096, K=1024] row-major; B = W_attn [N=3072, K=1024] row-major.
// 128x128 tile, BK=16, 256 threads, 8x8 per thread.
// ---------------------------------------------------------------------------
__global__ __launch_bounds__(256) void qkv_gemm_kernel(
    const float* __restrict__ A, const float* __restrict__ B)
{
    __shared__ float As[16][128];
    __shared__ float Bs[16][128];
    const int m0 = blockIdx.y * 128;
    const int n0 = blockIdx.x * 128;
    const int tid = threadIdx.x;
    const int ty = tid >> 4, tx = tid & 15;

    float acc[8][8];
#pragma unroll
    for (int i = 0; i < 8; i++)
#pragma unroll
        for (int j = 0; j < 8; j++) acc[i][j] = 0.f;

    for (int kt = 0; kt < NC; kt += 16) {
#pragma unroll
        for (int i = 0; i < 2; i++) {
            int lin = tid + i * 256;          // 0..511
            int row = lin >> 2;               // 0..127
            int k4  = (lin & 3) * 4;          // 0,4,8,12
            float4 av = *(const float4*)(A + (size_t)(m0 + row) * NC + kt + k4);
            As[k4+0][row] = av.x; As[k4+1][row] = av.y;
            As[k4+2][row] = av.z; As[k4+3][row] = av.w;
            float4 bv = *(const float4*)(B + (size_t)(n0 + row) * NC + kt + k4);
            Bs[k4+0][row] = bv.x; Bs[k4+1][row] = bv.y;
            Bs[k4+2][row] = bv.z; Bs[k4+3][row] = bv.w;
        }
        __syncthreads();
#pragma unroll 8
        for (int kk = 0; kk < 16; kk++) {
            float a[8], b[8];
            *(float4*)&a[0] = *(const float4*)&As[kk][ty * 8];
            *(float4*)&a[4] = *(const float4*)&As[kk][ty * 8 + 4];
            *(float4*)&b[0] = *(const float4*)&Bs[kk][tx * 8];
            *(float4*)&b[4] = *(const float4*)&Bs[kk][tx * 8 + 4];
#pragma unroll
            for (int i = 0; i < 8; i++)
#pragma unroll
                for (int j = 0; j < 8; j++) acc[i][j] += a[i] * b[j];
        }
        __syncthreads();
    }

    // Epilogue: scatter to Q/K/V in [B,H,T,d]. Each thread's 8 n-values
    // stay within one 64-wide head segment (tx*8 aligned, 8 | 64).
    const int nbase = n0 + tx * 8;
    const int sel = nbase >> 10;          // 0=Q 1=K 2=V
    const int c   = nbase & 1023;
    const int h   = c >> 6;
    const int dd  = c & 63;
    float* dst = (sel == 0) ? g_Q : (sel == 1) ? g_K : g_V;
#pragma unroll
    for (int i = 0; i < 8; i++) {
        int m = m0 + ty * 8 + i;
        int b = m >> 11;                  // /2048
        int t = m & 2047;
        float* p = dst + ((size_t)((b * NH + h) * NT) + t) * ND + dd;
        *(float4*)(p)     = make_float4(acc[i][0], acc[i][1], acc[i][2], acc[i][3]);
        *(float4*)(p + 4) = make_float4(acc[i][4], acc[i][5], acc[i][6], acc[i][7]);
    }
}

// ---------------------------------------------------------------------------
// Kernel 2: flash attention, fp32, no mask.
// grid = (T/128, B*H), 256 threads. BM=128 queries, BN=64 keys per iter.
// Thread grid 16x16: each thread owns 8 score rows x 4 cols, 8x4 of O.
// Smem: Qs[128][64], Ks[64(d)][64(key)] (transposed), Vs[64][64], Ps[128][64].
// ---------------------------------------------------------------------------
__global__ __launch_bounds__(256, 2) void attn_kernel()
{
    extern __shared__ float sm[];
    float* Qs = sm;                       // 128*64
    float* Ks = Qs + 128 * 64;            // 64*64  [dd][key]
    float* Vs = Ks + 64 * 64;             // 64*64  [key][dd]
    float* Ps = Vs + 64 * 64;             // 128*64 [row][key]

    const int bh = blockIdx.y;
    const int q0 = blockIdx.x * 128;
    const float* Qg = g_Q + (size_t)bh * NT * ND;
    const float* Kg = g_K + (size_t)bh * NT * ND;
    const float* Vg = g_V + (size_t)bh * NT * ND;

    const int tid = threadIdx.x;
    const int ty = tid >> 4, tx = tid & 15;
    const float scale = 0.125f;           // 1/sqrt(64)

    // Load Q tile, pre-scaled (visibility covered by first in-loop sync).
#pragma unroll
    for (int i = 0; i < 8; i++) {
        int lin = tid + i * 256;          // 0..2047
        int row = lin >> 4;
        int c4  = (lin & 15) * 4;
        float4 v = *(const float4*)(Qg + (size_t)(q0 + row) * ND + c4);
        v.x *= scale; v.y *= scale; v.z *= scale; v.w *= scale;
        *(float4*)(Qs + row * 64 + c4) = v;
    }

    float m_i[8], l_i[8], O[8][4];
#pragma unroll
    for (int i = 0; i < 8; i++) {
        m_i[i] = -1e30f; l_i[i] = 0.f;
#pragma unroll
        for (int j = 0; j < 4; j++) O[i][j] = 0.f;
    }

    for (int kb = 0; kb < NT / 64; kb++) {
        const int k0 = kb * 64;
        // Load K (transposed to [dd][key]) and V ([key][dd]).
#pragma unroll
        for (int i = 0; i < 4; i++) {
            int lin = tid + i * 256;      // 0..1023
            int key = lin >> 4;
            int c4  = (lin & 15) * 4;
            float4 kv = *(const float4*)(Kg + (size_t)(k0 + key) * ND + c4);
            Ks[(c4 + 0) * 64 + key] = kv.x;
            Ks[(c4 + 1) * 64 + key] = kv.y;
            Ks[(c4 + 2) * 64 + key] = kv.z;
            Ks[(c4 + 3) * 64 + key] = kv.w;
            float4 vv = *(const float4*)(Vg + (size_t)(k0 + key) * ND + c4);
            *(float4*)(Vs + key * 64 + c4) = vv;
        }
        __syncthreads();

        // S = Qs @ Ks  (already scaled)
        float s[8][4];
#pragma unroll
        for (int i = 0; i < 8; i++)
#pragma unroll
            for (int j = 0; j < 4; j++) s[i][j] = 0.f;
#pragma unroll 8
        for (int dd = 0; dd < 64; dd++) {
            float a[8];
#pragma unroll
            for (int i = 0; i < 8; i++) a[i] = Qs[(ty * 8 + i) * 64 + dd];
            float bq[4];
            *(float4*)bq = *(const float4*)(Ks + dd * 64 + tx * 4);
#pragma unroll
            for (int i = 0; i < 8; i++)
#pragma unroll
                for (int j = 0; j < 4; j++) s[i][j] += a[i] * bq[j];
        }

        // Online softmax. 16-lane butterfly: lanes with the same ty occupy a
        // contiguous 16-lane half (lane = (ty&1)*16 + tx), so xor 1..8 stays
        // within the row group.
#pragma unroll
        for (int i = 0; i < 8; i++) {
            float mt = fmaxf(fmaxf(s[i][0], s[i][1]), fmaxf(s[i][2], s[i][3]));
#pragma unroll
            for (int off = 1; off < 16; off <<= 1)
                mt = fmaxf(mt, __shfl_xor_sync(0xffffffffu, mt, off));
            float mn = fmaxf(m_i[i], mt);
            float alpha = __expf(m_i[i] - mn);
            m_i[i] = mn;
            float rs = 0.f;
#pragma unroll
            for (int j = 0; j < 4; j++) {
                float p = __expf(s[i][j] - mn);
                s[i][j] = p;
                rs += p;
            }
#pragma unroll
            for (int off = 1; off < 16; off <<= 1)
                rs += __shfl_xor_sync(0xffffffffu, rs, off);
            l_i[i] = l_i[i] * alpha + rs;
#pragma unroll
            for (int j = 0; j < 4; j++) O[i][j] *= alpha;
            *(float4*)(Ps + (ty * 8 + i) * 64 + tx * 4) = *(float4*)&s[i][0];
        }
        __syncthreads();

        // O += P @ V
#pragma unroll 8
        for (int kk = 0; kk < 64; kk++) {
            float p[8];
#pragma unroll
            for (int i = 0; i < 8; i++) p[i] = Ps[(ty * 8 + i) * 64 + kk];
            float v4[4];
            *(float4*)v4 = *(const float4*)(Vs + kk * 64 + tx * 4);
#pragma unroll
            for (int i = 0; i < 8; i++)
#pragma unroll
                for (int j = 0; j < 4; j++) O[i][j] += p[i] * v4[j];
        }
        __syncthreads();
    }

    // Epilogue: normalize and write into [B,T,C] layout for the proj GEMM.
    const int b = bh >> 4, h = bh & 15;
#pragma unroll
    for (int i = 0; i < 8; i++) {
        float inv = 1.0f / l_i[i];
        int t = q0 + ty * 8 + i;
        float4 o = make_float4(O[i][0] * inv, O[i][1] * inv,
                               O[i][2] * inv, O[i][3] * inv);
        *(float4*)(g_Y + (size_t)(b * NT + t) * NC + h * 64 + tx * 4) = o;
    }
}

// ---------------------------------------------------------------------------
// Kernel 3: out = Y @ W_proj^T + b_proj.  A = g_Y [4096,1024], B [1024,1024].
// ---------------------------------------------------------------------------
__global__ __launch_bounds__(256) void proj_gemm_kernel(
    const float* __restrict__ B, const float* __restrict__ bias,
    float* __restrict__ out)
{
    __shared__ float As[16][128];
    __shared__ float Bs[16][128];
    const int m0 = blockIdx.y * 128;
    const int n0 = blockIdx.x * 128;
    const int tid = threadIdx.x;
    const int ty = tid >> 4, tx = tid & 15;
    const float* A = g_Y;

    float acc[8][8];
#pragma unroll
    for (int i = 0; i < 8; i++)
#pragma unroll
        for (int j = 0; j < 8; j++) acc[i][j] = 0.f;

    for (int kt = 0; kt < NC; kt += 16) {
#pragma unroll
        for (int i = 0; i < 2; i++) {
            int lin = tid + i * 256;
            int row = lin >> 2;
            int k4  = (lin & 3) * 4;
            float4 av = *(const float4*)(A + (size_t)(m0 + row) * NC + kt + k4);
            As[k4+0][row] = av.x; As[k4+1][row] = av.y;
            As[k4+2][row] = av.z; As[k4+3][row] = av.w;
            float4 bv = *(const float4*)(B + (size_t)(n0 + row) * NC + kt + k4);
            Bs[k4+0][row] = bv.x; Bs[k4+1][row] = bv.y;
            Bs[k4+2][row] = bv.z; Bs[k4+3][row] = bv.w;
        }
        __syncthreads();
#pragma unroll 8
        for (int kk = 0; kk < 16; kk++) {
            float a[8], b[8];
            *(float4*)&a[0] = *(const float4*)&As[kk][ty * 8];
            *(float4*)&a[4] = *(const float4*)&As[kk][ty * 8 + 4];
            *(float4*)&b[0] = *(const float4*)&Bs[kk][tx * 8];
            *(float4*)&b[4] = *(const float4*)&Bs[kk][tx * 8 + 4];
#pragma unroll
            for (int i = 0; i < 8; i++)
#pragma unroll
                for (int j = 0; j < 8; j++) acc[i][j] += a[i] * b[j];
        }
        __syncthreads();
    }

    const int n = n0 + tx * 8;
    float4 bb0 = *(const float4*)(bias + n);
    float4 bb1 = *(const float4*)(bias + n + 4);
#pragma unroll
    for (int i = 0; i < 8; i++) {
        int m = m0 + ty * 8 + i;
        float4 o0 = make_float4(acc[i][0] + bb0.x, acc[i][1] + bb0.y,
                                acc[i][2] + bb0.z, acc[i][3] + bb0.w);
        float4 o1 = make_float4(acc[i][4] + bb1.x, acc[i][5] + bb1.y,
                                acc[i][6] + bb1.z, acc[i][7] + bb1.w);
        *(float4*)(out + (size_t)m * NC + n)     = o0;
        *(float4*)(out + (size_t)m * NC + n + 4) = o1;
    }
}

// ---------------------------------------------------------------------------
extern "C" void kernel_launch(void* const* d_in, const int* in_sizes, int n_in,
                              void* d_out, int out_size)
{
    const float* x      = (const float*)d_in[0];
    const float* W_attn = (const float*)d_in[1];
    const float* W_proj = (const float*)d_in[2];
    const float* b_proj = (const float*)d_in[3];
    float* out = (float*)d_out;

    // 1) QKV projection + scatter to [B,H,T,d]
    qkv_gemm_kernel<<<dim3(3 * NC / 128, MTOT / 128), 256>>>(x, W_attn);

    // 2) Flash attention (96 KB dynamic smem)
    size_t smem = (size_t)(128 * 64 + 64 * 64 + 64 * 64 + 128 * 64) * sizeof(float);
    cudaFuncSetAttribute(attn_kernel,
                         cudaFuncAttributeMaxDynamicSharedMemorySize, (int)smem);
    attn_kernel<<<dim3(NT / 128, NB * NH), 256, smem>>>();

    // 3) Output projection + bias
    proj_gemm_kernel<<<dim3(NC / 128, MTOT / 128), 256>>>(W_proj, b_proj, out);
}

// round 4
// speedup vs baseline: 1.0002x; 1.0002x over previous
#include <cuda_runtime.h>
#include <math.h>

#define NH 16
#define NB 2
#define NT 2048
#define NC 1024
#define ND 64
#define MTOT (NB*NT)   // 4096

// Scratch (allocation-free rule: __device__ globals). 16 MB each.
__device__ float g_Q[(size_t)NB*NH*NT*ND];
__device__ float g_K[(size_t)NB*NH*NT*ND];
__device__ float g_V[(size_t)NB*NH*NT*ND];
__device__ float g_Y[(size_t)MTOT*NC];

// ---------------------------------------------------------------------------
// Kernel 1: qkv = x @ W_attn^T, scattered into Q/K/V as [B,H,T,d].
// A = x [M=4096, K=1024] row-major; B = W_attn [N=3072, K=1024] row-major.
// 128x128 tile, BK=16, 256 threads, 8x8 per thread.
// ---------------------------------------------------------------------------
__global__ __launch_bounds__(256) void qkv_gemm_kernel(
    const float* __restrict__ A, const float* __restrict__ B)
{
    __shared__ float As[16][128];
    __shared__ float Bs[16][128];
    const int m0 = blockIdx.y * 128;
    const int n0 = blockIdx.x * 128;
    const int tid = threadIdx.x;
    const int ty = tid >> 4, tx = tid & 15;

    float acc[8][8];
#pragma unroll
    for (int i = 0; i < 8; i++)
#pragma unroll
        for (int j = 0; j < 8; j++) acc[i][j] = 0.f;

    for (int kt = 0; kt < NC; kt += 16) {
#pragma unroll
        for (int i = 0; i < 2; i++) {
            int lin = tid + i * 256;          // 0..511
            int row = lin >> 2;               // 0..127
            int k4  = (lin & 3) * 4;          // 0,4,8,12
            float4 av = *(const float4*)(A + (size_t)(m0 + row) * NC + kt + k4);
            As[k4+0][row] = av.x; As[k4+1][row] = av.y;
            As[k4+2][row] = av.z; As[k4+3][row] = av.w;
            float4 bv = *(const float4*)(B + (size_t)(n0 + row) * NC + kt + k4);
            Bs[k4+0][row] = bv.x; Bs[k4+1][row] = bv.y;
            Bs[k4+2][row] = bv.z; Bs[k4+3][row] = bv.w;
        }
        __syncthreads();
#pragma unroll 8
        for (int kk = 0; kk < 16; kk++) {
            float a[8], b[8];
            *(float4*)&a[0] = *(const float4*)&As[kk][ty * 8];
            *(float4*)&a[4] = *(const float4*)&As[kk][ty * 8 + 4];
            *(float4*)&b[0] = *(const float4*)&Bs[kk][tx * 8];
            *(float4*)&b[4] = *(const float4*)&Bs[kk][tx * 8 + 4];
#pragma unroll
            for (int i = 0; i < 8; i++)
#pragma unroll
                for (int j = 0; j < 8; j++) acc[i][j] += a[i] * b[j];
        }
        __syncthreads();
    }

    // Epilogue: scatter to Q/K/V in [B,H,T,d]. Each thread's 8 n-values
    // stay within one 64-wide head segment (tx*8 aligned, 8 | 64).
    const int nbase = n0 + tx * 8;
    const int sel = nbase >> 10;          // 0=Q 1=K 2=V
    const int c   = nbase & 1023;
    const int h   = c >> 6;
    const int dd  = c & 63;
    float* dst = (sel == 0) ? g_Q : (sel == 1) ? g_K : g_V;
#pragma unroll
    for (int i = 0; i < 8; i++) {
        int m = m0 + ty * 8 + i;
        int b = m >> 11;                  // /2048
        int t = m & 2047;
        float* p = dst + ((size_t)((b * NH + h) * NT) + t) * ND + dd;
        *(float4*)(p)     = make_float4(acc[i][0], acc[i][1], acc[i][2], acc[i][3]);
        *(float4*)(p + 4) = make_float4(acc[i][4], acc[i][5], acc[i][6], acc[i][7]);
    }
}

// ---------------------------------------------------------------------------
// Kernel 2: flash attention, fp32, no mask.
// grid = (T/128, B*H), 256 threads. BM=128 queries, BN=64 keys per iter.
// Thread grid 16x16: each thread owns 8 score rows x 4 cols, 8x4 of O.
// Smem: Qs[128][64], Ks[64(d)][64(key)] (transposed), Vs[64][64], Ps[128][64].
// ---------------------------------------------------------------------------
__global__ __launch_bounds__(256, 2) void attn_kernel()
{
    extern __shared__ float sm[];
    float* Qs = sm;                       // 128*64
    float* Ks = Qs + 128 * 64;            // 64*64  [dd][key]
    float* Vs = Ks + 64 * 64;             // 64*64  [key][dd]
    float* Ps = Vs + 64 * 64;             // 128*64 [row][key]

    const int bh = blockIdx.y;
    const int q0 = blockIdx.x * 128;
    const float* Qg = g_Q + (size_t)bh * NT * ND;
    const float* Kg = g_K + (size_t)bh * NT * ND;
    const float* Vg = g_V + (size_t)bh * NT * ND;

    const int tid = threadIdx.x;
    const int ty = tid >> 4, tx = tid & 15;
    const float scale = 0.125f;           // 1/sqrt(64)

    // Load Q tile, pre-scaled (visibility covered by first in-loop sync).
#pragma unroll
    for (int i = 0; i < 8; i++) {
        int lin = tid + i * 256;          // 0..2047
        int row = lin >> 4;
        int c4  = (lin & 15) * 4;
        float4 v = *(const float4*)(Qg + (size_t)(q0 + row) * ND + c4);
        v.x *= scale; v.y *= scale; v.z *= scale; v.w *= scale;
        *(float4*)(Qs + row * 64 + c4) = v;
    }

    float m_i[8], l_i[8], O[8][4];
#pragma unroll
    for (int i = 0; i < 8; i++) {
        m_i[i] = -1e30f; l_i[i] = 0.f;
#pragma unroll
        for (int j = 0; j < 4; j++) O[i][j] = 0.f;
    }

    for (int kb = 0; kb < NT / 64; kb++) {
        const int k0 = kb * 64;
        // Load K (transposed to [dd][key]) and V ([key][dd]).
#pragma unroll
        for (int i = 0; i < 4; i++) {
            int lin = tid + i * 256;      // 0..1023
            int key = lin >> 4;
            int c4  = (lin & 15) * 4;
            float4 kv = *(const float4*)(Kg + (size_t)(k0 + key) * ND + c4);
            Ks[(c4 + 0) * 64 + key] = kv.x;
            Ks[(c4 + 1) * 64 + key] = kv.y;
            Ks[(c4 + 2) * 64 + key] = kv.z;
            Ks[(c4 + 3) * 64 + key] = kv.w;
            float4 vv = *(const float4*)(Vg + (size_t)(k0 + key) * ND + c4);
            *(float4*)(Vs + key * 64 + c4) = vv;
        }
        __syncthreads();

        // S = Qs @ Ks  (already scaled)
        float s[8][4];
#pragma unroll
        for (int i = 0; i < 8; i++)
#pragma unroll
            for (int j = 0; j < 4; j++) s[i][j] = 0.f;
#pragma unroll 8
        for (int dd = 0; dd < 64; dd++) {
            float a[8];
#pragma unroll
            for (int i = 0; i < 8; i++) a[i] = Qs[(ty * 8 + i) * 64 + dd];
            float bq[4];
            *(float4*)bq = *(const float4*)(Ks + dd * 64 + tx * 4);
#pragma unroll
            for (int i = 0; i < 8; i++)
#pragma unroll
                for (int j = 0; j < 4; j++) s[i][j] += a[i] * bq[j];
        }

        // Online softmax. 16-lane butterfly: lanes with the same ty occupy a
        // contiguous 16-lane half (lane = (ty&1)*16 + tx), so xor 1..8 stays
        // within the row group.
#pragma unroll
        for (int i = 0; i < 8; i++) {
            float mt = fmaxf(fmaxf(s[i][0], s[i][1]), fmaxf(s[i][2], s[i][3]));
#pragma unroll
            for (int off = 1; off < 16; off <<= 1)
                mt = fmaxf(mt, __shfl_xor_sync(0xffffffffu, mt, off));
            float mn = fmaxf(m_i[i], mt);
            float alpha = __expf(m_i[i] - mn);
            m_i[i] = mn;
            float rs = 0.f;
#pragma unroll
            for (int j = 0; j < 4; j++) {
                float p = __expf(s[i][j] - mn);
                s[i][j] = p;
                rs += p;
            }
#pragma unroll
            for (int off = 1; off < 16; off <<= 1)
                rs += __shfl_xor_sync(0xffffffffu, rs, off);
            l_i[i] = l_i[i] * alpha + rs;
#pragma unroll
            for (int j = 0; j < 4; j++) O[i][j] *= alpha;
            *(float4*)(Ps + (ty * 8 + i) * 64 + tx * 4) = *(float4*)&s[i][0];
        }
        __syncthreads();

        // O += P @ V
#pragma unroll 8
        for (int kk = 0; kk < 64; kk++) {
            float p[8];
#pragma unroll
            for (int i = 0; i < 8; i++) p[i] = Ps[(ty * 8 + i) * 64 + kk];
            float v4[4];
            *(float4*)v4 = *(const float4*)(Vs + kk * 64 + tx * 4);
#pragma unroll
            for (int i = 0; i < 8; i++)
#pragma unroll
                for (int j = 0; j < 4; j++) O[i][j] += p[i] * v4[j];
        }
        __syncthreads();
    }

    // Epilogue: normalize and write into [B,T,C] layout for the proj GEMM.
    const int b = bh >> 4, h = bh & 15;
#pragma unroll
    for (int i = 0; i < 8; i++) {
        float inv = 1.0f / l_i[i];
        int t = q0 + ty * 8 + i;
        float4 o = make_float4(O[i][0] * inv, O[i][1] * inv,
                               O[i][2] * inv, O[i][3] * inv);
        *(float4*)(g_Y + (size_t)(b * NT + t) * NC + h * 64 + tx * 4) = o;
    }
}

// ---------------------------------------------------------------------------
// Kernel 3: out = Y @ W_proj^T + b_proj.  A = g_Y [4096,1024], B [1024,1024].
// ---------------------------------------------------------------------------
__global__ __launch_bounds__(256) void proj_gemm_kernel(
    const float* __restrict__ B, const float* __restrict__ bias,
    float* __restrict__ out)
{
    __shared__ float As[16][128];
    __shared__ float Bs[16][128];
    const int m0 = blockIdx.y * 128;
    const int n0 = blockIdx.x * 128;
    const int tid = threadIdx.x;
    const int ty = tid >> 4, tx = tid & 15;
    const float* A = g_Y;

    float acc[8][8];
#pragma unroll
    for (int i = 0; i < 8; i++)
#pragma unroll
        for (int j = 0; j < 8; j++) acc[i][j] = 0.f;

    for (int kt = 0; kt < NC; kt += 16) {
#pragma unroll
        for (int i = 0; i < 2; i++) {
            int lin = tid + i * 256;
            int row = lin >> 2;
            int k4  = (lin & 3) * 4;
            float4 av = *(const float4*)(A + (size_t)(m0 + row) * NC + kt + k4);
            As[k4+0][row] = av.x; As[k4+1][row] = av.y;
            As[k4+2][row] = av.z; As[k4+3][row] = av.w;
            float4 bv = *(const float4*)(B + (size_t)(n0 + row) * NC + kt + k4);
            Bs[k4+0][row] = bv.x; Bs[k4+1][row] = bv.y;
            Bs[k4+2][row] = bv.z; Bs[k4+3][row] = bv.w;
        }
        __syncthreads();
#pragma unroll 8
        for (int kk = 0; kk < 16; kk++) {
            float a[8], b[8];
            *(float4*)&a[0] = *(const float4*)&As[kk][ty * 8];
            *(float4*)&a[4] = *(const float4*)&As[kk][ty * 8 + 4];
            *(float4*)&b[0] = *(const float4*)&Bs[kk][tx * 8];
            *(float4*)&b[4] = *(const float4*)&Bs[kk][tx * 8 + 4];
#pragma unroll
            for (int i = 0; i < 8; i++)
#pragma unroll
                for (int j = 0; j < 8; j++) acc[i][j] += a[i] * b[j];
        }
        __syncthreads();
    }

    const int n = n0 + tx * 8;
    float4 bb0 = *(const float4*)(bias + n);
    float4 bb1 = *(const float4*)(bias + n + 4);
#pragma unroll
    for (int i = 0; i < 8; i++) {
        int m = m0 + ty * 8 + i;
        float4 o0 = make_float4(acc[i][0] + bb0.x, acc[i][1] + bb0.y,
                                acc[i][2] + bb0.z, acc[i][3] + bb0.w);
        float4 o1 = make_float4(acc[i][4] + bb1.x, acc[i][5] + bb1.y,
                                acc[i][6] + bb1.z, acc[i][7] + bb1.w);
        *(float4*)(out + (size_t)m * NC + n)     = o0;
        *(float4*)(out + (size_t)m * NC + n + 4) = o1;
    }
}

// ---------------------------------------------------------------------------
extern "C" void kernel_launch(void* const* d_in, const int* in_sizes, int n_in,
                              void* d_out, int out_size)
{
    const float* x      = (const float*)d_in[0];
    const float* W_attn = (const float*)d_in[1];
    const float* W_proj = (const float*)d_in[2];
    const float* b_proj = (const float*)d_in[3];
    float* out = (float*)d_out;

    // 1) QKV projection + scatter to [B,H,T,d]
    qkv_gemm_kernel<<<dim3(3 * NC / 128, MTOT / 128), 256>>>(x, W_attn);

    // 2) Flash attention (96 KB dynamic smem)
    size_t smem = (size_t)(128 * 64 + 64 * 64 + 64 * 64 + 128 * 64) * sizeof(float);
    cudaFuncSetAttribute(attn_kernel,
                         cudaFuncAttributeMaxDynamicSharedMemorySize, (int)smem);
    attn_kernel<<<dim3(NT / 128, NB * NH), 256, smem>>>();

    // 3) Output projection + bias
    proj_gemm_kernel<<<dim3(NC / 128, MTOT / 128), 256>>>(W_proj, b_proj, out);
}

// round 5
// speedup vs baseline: 1.0004x; 1.0002x over previous
#include <cuda_runtime.h>
#include <math.h>

#define NH 16
#define NB 2
#define NT 2048
#define NC 1024
#define ND 64
#define MTOT (NB*NT)   // 4096

// Scratch (allocation-free rule: __device__ globals). 16 MB each.
__device__ float g_Q[(size_t)NB*NH*NT*ND];
__device__ float g_K[(size_t)NB*NH*NT*ND];
__device__ float g_V[(size_t)NB*NH*NT*ND];
__device__ float g_Y[(size_t)MTOT*NC];

// ---------------------------------------------------------------------------
// Kernel 1: qkv = x @ W_attn^T, scattered into Q/K/V as [B,H,T,d].
// A = x [M=4096, K=1024] row-major; B = W_attn [N=3072, K=1024] row-major.
// 128x128 tile, BK=16, 256 threads, 8x8 per thread.
// ---------------------------------------------------------------------------
__global__ __launch_bounds__(256) void qkv_gemm_kernel(
    const float* __restrict__ A, const float* __restrict__ B)
{
    __shared__ float As[16][128];
    __shared__ float Bs[16][128];
    const int m0 = blockIdx.y * 128;
    const int n0 = blockIdx.x * 128;
    const int tid = threadIdx.x;
    const int ty = tid >> 4, tx = tid & 15;

    float acc[8][8];
#pragma unroll
    for (int i = 0; i < 8; i++)
#pragma unroll
        for (int j = 0; j < 8; j++) acc[i][j] = 0.f;

    for (int kt = 0; kt < NC; kt += 16) {
#pragma unroll
        for (int i = 0; i < 2; i++) {
            int lin = tid + i * 256;          // 0..511
            int row = lin >> 2;               // 0..127
            int k4  = (lin & 3) * 4;          // 0,4,8,12
            float4 av = *(const float4*)(A + (size_t)(m0 + row) * NC + kt + k4);
            As[k4+0][row] = av.x; As[k4+1][row] = av.y;
            As[k4+2][row] = av.z; As[k4+3][row] = av.w;
            float4 bv = *(const float4*)(B + (size_t)(n0 + row) * NC + kt + k4);
            Bs[k4+0][row] = bv.x; Bs[k4+1][row] = bv.y;
            Bs[k4+2][row] = bv.z; Bs[k4+3][row] = bv.w;
        }
        __syncthreads();
#pragma unroll 8
        for (int kk = 0; kk < 16; kk++) {
            float a[8], b[8];
            *(float4*)&a[0] = *(const float4*)&As[kk][ty * 8];
            *(float4*)&a[4] = *(const float4*)&As[kk][ty * 8 + 4];
            *(float4*)&b[0] = *(const float4*)&Bs[kk][tx * 8];
            *(float4*)&b[4] = *(const float4*)&Bs[kk][tx * 8 + 4];
#pragma unroll
            for (int i = 0; i < 8; i++)
#pragma unroll
                for (int j = 0; j < 8; j++) acc[i][j] += a[i] * b[j];
        }
        __syncthreads();
    }

    // Epilogue: scatter to Q/K/V in [B,H,T,d]. Each thread's 8 n-values
    // stay within one 64-wide head segment (tx*8 aligned, 8 | 64).
    const int nbase = n0 + tx * 8;
    const int sel = nbase >> 10;          // 0=Q 1=K 2=V
    const int c   = nbase & 1023;
    const int h   = c >> 6;
    const int dd  = c & 63;
    float* dst = (sel == 0) ? g_Q : (sel == 1) ? g_K : g_V;
#pragma unroll
    for (int i = 0; i < 8; i++) {
        int m = m0 + ty * 8 + i;
        int b = m >> 11;                  // /2048
        int t = m & 2047;
        float* p = dst + ((size_t)((b * NH + h) * NT) + t) * ND + dd;
        *(float4*)(p)     = make_float4(acc[i][0], acc[i][1], acc[i][2], acc[i][3]);
        *(float4*)(p + 4) = make_float4(acc[i][4], acc[i][5], acc[i][6], acc[i][7]);
    }
}

// ---------------------------------------------------------------------------
// Kernel 2: flash attention, fp32, no mask.
// grid = (T/128, B*H), 256 threads. BM=128 queries, BN=64 keys per iter.
// Thread grid 16x16: each thread owns 8 score rows x 4 cols, 8x4 of O.
// Smem: Qs[128][64], Ks[64(d)][64(key)] (transposed), Vs[64][64], Ps[128][64].
// ---------------------------------------------------------------------------
__global__ __launch_bounds__(256, 2) void attn_kernel()
{
    extern __shared__ float sm[];
    float* Qs = sm;                       // 128*64
    float* Ks = Qs + 128 * 64;            // 64*64  [dd][key]
    float* Vs = Ks + 64 * 64;             // 64*64  [key][dd]
    float* Ps = Vs + 64 * 64;             // 128*64 [row][key]

    const int bh = blockIdx.y;
    const int q0 = blockIdx.x * 128;
    const float* Qg = g_Q + (size_t)bh * NT * ND;
    const float* Kg = g_K + (size_t)bh * NT * ND;
    const float* Vg = g_V + (size_t)bh * NT * ND;

    const int tid = threadIdx.x;
    const int ty = tid >> 4, tx = tid & 15;
    const float scale = 0.125f;           // 1/sqrt(64)

    // Load Q tile, pre-scaled (visibility covered by first in-loop sync).
#pragma unroll
    for (int i = 0; i < 8; i++) {
        int lin = tid + i * 256;          // 0..2047
        int row = lin >> 4;
        int c4  = (lin & 15) * 4;
        float4 v = *(const float4*)(Qg + (size_t)(q0 + row) * ND + c4);
        v.x *= scale; v.y *= scale; v.z *= scale; v.w *= scale;
        *(float4*)(Qs + row * 64 + c4) = v;
    }

    float m_i[8], l_i[8], O[8][4];
#pragma unroll
    for (int i = 0; i < 8; i++) {
        m_i[i] = -1e30f; l_i[i] = 0.f;
#pragma unroll
        for (int j = 0; j < 4; j++) O[i][j] = 0.f;
    }

    for (int kb = 0; kb < NT / 64; kb++) {
        const int k0 = kb * 64;
        // Load K (transposed to [dd][key]) and V ([key][dd]).
#pragma unroll
        for (int i = 0; i < 4; i++) {
            int lin = tid + i * 256;      // 0..1023
            int key = lin >> 4;
            int c4  = (lin & 15) * 4;
            float4 kv = *(const float4*)(Kg + (size_t)(k0 + key) * ND + c4);
            Ks[(c4 + 0) * 64 + key] = kv.x;
            Ks[(c4 + 1) * 64 + key] = kv.y;
            Ks[(c4 + 2) * 64 + key] = kv.z;
            Ks[(c4 + 3) * 64 + key] = kv.w;
            float4 vv = *(const float4*)(Vg + (size_t)(k0 + key) * ND + c4);
            *(float4*)(Vs + key * 64 + c4) = vv;
        }
        __syncthreads();

        // S = Qs @ Ks  (already scaled)
        float s[8][4];
#pragma unroll
        for (int i = 0; i < 8; i++)
#pragma unroll
            for (int j = 0; j < 4; j++) s[i][j] = 0.f;
#pragma unroll 8
        for (int dd = 0; dd < 64; dd++) {
            float a[8];
#pragma unroll
            for (int i = 0; i < 8; i++) a[i] = Qs[(ty * 8 + i) * 64 + dd];
            float bq[4];
            *(float4*)bq = *(const float4*)(Ks + dd * 64 + tx * 4);
#pragma unroll
            for (int i = 0; i < 8; i++)
#pragma unroll
                for (int j = 0; j < 4; j++) s[i][j] += a[i] * bq[j];
        }

        // Online softmax. 16-lane butterfly: lanes with the same ty occupy a
        // contiguous 16-lane half (lane = (ty&1)*16 + tx), so xor 1..8 stays
        // within the row group.
#pragma unroll
        for (int i = 0; i < 8; i++) {
            float mt = fmaxf(fmaxf(s[i][0], s[i][1]), fmaxf(s[i][2], s[i][3]));
#pragma unroll
            for (int off = 1; off < 16; off <<= 1)
                mt = fmaxf(mt, __shfl_xor_sync(0xffffffffu, mt, off));
            float mn = fmaxf(m_i[i], mt);
            float alpha = __expf(m_i[i] - mn);
            m_i[i] = mn;
            float rs = 0.f;
#pragma unroll
            for (int j = 0; j < 4; j++) {
                float p = __expf(s[i][j] - mn);
                s[i][j] = p;
                rs += p;
            }
#pragma unroll
            for (int off = 1; off < 16; off <<= 1)
                rs += __shfl_xor_sync(0xffffffffu, rs, off);
            l_i[i] = l_i[i] * alpha + rs;
#pragma unroll
            for (int j = 0; j < 4; j++) O[i][j] *= alpha;
            *(float4*)(Ps + (ty * 8 + i) * 64 + tx * 4) = *(float4*)&s[i][0];
        }
        __syncthreads();

        // O += P @ V
#pragma unroll 8
        for (int kk = 0; kk < 64; kk++) {
            float p[8];
#pragma unroll
            for (int i = 0; i < 8; i++) p[i] = Ps[(ty * 8 + i) * 64 + kk];
            float v4[4];
            *(float4*)v4 = *(const float4*)(Vs + kk * 64 + tx * 4);
#pragma unroll
            for (int i = 0; i < 8; i++)
#pragma unroll
                for (int j = 0; j < 4; j++) O[i][j] += p[i] * v4[j];
        }
        __syncthreads();
    }

    // Epilogue: normalize and write into [B,T,C] layout for the proj GEMM.
    const int b = bh >> 4, h = bh & 15;
#pragma unroll
    for (int i = 0; i < 8; i++) {
        float inv = 1.0f / l_i[i];
        int t = q0 + ty * 8 + i;
        float4 o = make_float4(O[i][0] * inv, O[i][1] * inv,
                               O[i][2] * inv, O[i][3] * inv);
        *(float4*)(g_Y + (size_t)(b * NT + t) * NC + h * 64 + tx * 4) = o;
    }
}

// ---------------------------------------------------------------------------
// Kernel 3: out = Y @ W_proj^T + b_proj.  A = g_Y [4096,1024], B [1024,1024].
// ---------------------------------------------------------------------------
__global__ __launch_bounds__(256) void proj_gemm_kernel(
    const float* __restrict__ B, const float* __restrict__ bias,
    float* __restrict__ out)
{
    __shared__ float As[16][128];
    __shared__ float Bs[16][128];
    const int m0 = blockIdx.y * 128;
    const int n0 = blockIdx.x * 128;
    const int tid = threadIdx.x;
    const int ty = tid >> 4, tx = tid & 15;
    const float* A = g_Y;

    float acc[8][8];
#pragma unroll
    for (int i = 0; i < 8; i++)
#pragma unroll
        for (int j = 0; j < 8; j++) acc[i][j] = 0.f;

    for (int kt = 0; kt < NC; kt += 16) {
#pragma unroll
        for (int i = 0; i < 2; i++) {
            int lin = tid + i * 256;
            int row = lin >> 2;
            int k4  = (lin & 3) * 4;
            float4 av = *(const float4*)(A + (size_t)(m0 + row) * NC + kt + k4);
            As[k4+0][row] = av.x; As[k4+1][row] = av.y;
            As[k4+2][row] = av.z; As[k4+3][row] = av.w;
            float4 bv = *(const float4*)(B + (size_t)(n0 + row) * NC + kt + k4);
            Bs[k4+0][row] = bv.x; Bs[k4+1][row] = bv.y;
            Bs[k4+2][row] = bv.z; Bs[k4+3][row] = bv.w;
        }
        __syncthreads();
#pragma unroll 8
        for (int kk = 0; kk < 16; kk++) {
            float a[8], b[8];
            *(float4*)&a[0] = *(const float4*)&As[kk][ty * 8];
            *(float4*)&a[4] = *(const float4*)&As[kk][ty * 8 + 4];
            *(float4*)&b[0] = *(const float4*)&Bs[kk][tx * 8];
            *(float4*)&b[4] = *(const float4*)&Bs[kk][tx * 8 + 4];
#pragma unroll
            for (int i = 0; i < 8; i++)
#pragma unroll
                for (int j = 0; j < 8; j++) acc[i][j] += a[i] * b[j];
        }
        __syncthreads();
    }

    const int n = n0 + tx * 8;
    float4 bb0 = *(const float4*)(bias + n);
    float4 bb1 = *(const float4*)(bias + n + 4);
#pragma unroll
    for (int i = 0; i < 8; i++) {
        int m = m0 + ty * 8 + i;
        float4 o0 = make_float4(acc[i][0] + bb0.x, acc[i][1] + bb0.y,
                                acc[i][2] + bb0.z, acc[i][3] + bb0.w);
        float4 o1 = make_float4(acc[i][4] + bb1.x, acc[i][5] + bb1.y,
                                acc[i][6] + bb1.z, acc[i][7] + bb1.w);
        *(float4*)(out + (size_t)m * NC + n)     = o0;
        *(float4*)(out + (size_t)m * NC + n + 4) = o1;
    }
}

// ---------------------------------------------------------------------------
extern "C" void kernel_launch(void* const* d_in, const int* in_sizes, int n_in,
                              void* d_out, int out_size)
{
    const float* x      = (const float*)d_in[0];
    const float* W_attn = (const float*)d_in[1];
    const float* W_proj = (const float*)d_in[2];
    const float* b_proj = (const float*)d_in[3];
    float* out = (float*)d_out;

    // 1) QKV projection + scatter to [B,H,T,d]
    qkv_gemm_kernel<<<dim3(3 * NC / 128, MTOT / 128), 256>>>(x, W_attn);

    // 2) Flash attention (96 KB dynamic smem)
    size_t smem = (size_t)(128 * 64 + 64 * 64 + 64 * 64 + 128 * 64) * sizeof(float);
    cudaFuncSetAttribute(attn_kernel,
                         cudaFuncAttributeMaxDynamicSharedMemorySize, (int)smem);
    attn_kernel<<<dim3(NT / 128, NB * NH), 256, smem>>>();

    // 3) Output projection + bias
    proj_gemm_kernel<<<dim3(NC / 128, MTOT / 128), 256>>>(W_proj, b_proj, out);
}

// round 6
// speedup vs baseline: 1.0009x; 1.0006x over previous
#include <cuda_runtime.h>
#include <math.h>

#define NH 16
#define NB 2
#define NT 2048
#define NC 1024
#define ND 64
#define MTOT (NB*NT)   // 4096

// Scratch (allocation-free rule: __device__ globals). 16 MB each.
__device__ float g_Q[(size_t)NB*NH*NT*ND];
__device__ float g_K[(size_t)NB*NH*NT*ND];
__device__ float g_V[(size_t)NB*NH*NT*ND];
__device__ float g_Y[(size_t)MTOT*NC];

// ---------------------------------------------------------------------------
// Kernel 1: qkv = x @ W_attn^T, scattered into Q/K/V as [B,H,T,d].
// A = x [M=4096, K=1024] row-major; B = W_attn [N=3072, K=1024] row-major.
// 128x128 tile, BK=16, 256 threads, 8x8 per thread.
// ---------------------------------------------------------------------------
__global__ __launch_bounds__(256) void qkv_gemm_kernel(
    const float* __restrict__ A, const float* __restrict__ B)
{
    __shared__ float As[16][128];
    __shared__ float Bs[16][128];
    const int m0 = blockIdx.y * 128;
    const int n0 = blockIdx.x * 128;
    const int tid = threadIdx.x;
    const int ty = tid >> 4, tx = tid & 15;

    float acc[8][8];
#pragma unroll
    for (int i = 0; i < 8; i++)
#pragma unroll
        for (int j = 0; j < 8; j++) acc[i][j] = 0.f;

    for (int kt = 0; kt < NC; kt += 16) {
#pragma unroll
        for (int i = 0; i < 2; i++) {
            int lin = tid + i * 256;          // 0..511
            int row = lin >> 2;               // 0..127
            int k4  = (lin & 3) * 4;          // 0,4,8,12
            float4 av = *(const float4*)(A + (size_t)(m0 + row) * NC + kt + k4);
            As[k4+0][row] = av.x; As[k4+1][row] = av.y;
            As[k4+2][row] = av.z; As[k4+3][row] = av.w;
            float4 bv = *(const float4*)(B + (size_t)(n0 + row) * NC + kt + k4);
            Bs[k4+0][row] = bv.x; Bs[k4+1][row] = bv.y;
            Bs[k4+2][row] = bv.z; Bs[k4+3][row] = bv.w;
        }
        __syncthreads();
#pragma unroll 8
        for (int kk = 0; kk < 16; kk++) {
            float a[8], b[8];
            *(float4*)&a[0] = *(const float4*)&As[kk][ty * 8];
            *(float4*)&a[4] = *(const float4*)&As[kk][ty * 8 + 4];
            *(float4*)&b[0] = *(const float4*)&Bs[kk][tx * 8];
            *(float4*)&b[4] = *(const float4*)&Bs[kk][tx * 8 + 4];
#pragma unroll
            for (int i = 0; i < 8; i++)
#pragma unroll
                for (int j = 0; j < 8; j++) acc[i][j] += a[i] * b[j];
        }
        __syncthreads();
    }

    // Epilogue: scatter to Q/K/V in [B,H,T,d]. Each thread's 8 n-values
    // stay within one 64-wide head segment (tx*8 aligned, 8 | 64).
    const int nbase = n0 + tx * 8;
    const int sel = nbase >> 10;          // 0=Q 1=K 2=V
    const int c   = nbase & 1023;
    const int h   = c >> 6;
    const int dd  = c & 63;
    float* dst = (sel == 0) ? g_Q : (sel == 1) ? g_K : g_V;
#pragma unroll
    for (int i = 0; i < 8; i++) {
        int m = m0 + ty * 8 + i;
        int b = m >> 11;                  // /2048
        int t = m & 2047;
        float* p = dst + ((size_t)((b * NH + h) * NT) + t) * ND + dd;
        *(float4*)(p)     = make_float4(acc[i][0], acc[i][1], acc[i][2], acc[i][3]);
        *(float4*)(p + 4) = make_float4(acc[i][4], acc[i][5], acc[i][6], acc[i][7]);
    }
}

// ---------------------------------------------------------------------------
// Kernel 2: flash attention, fp32, no mask.
// grid = (T/128, B*H), 256 threads. BM=128 queries, BN=64 keys per iter.
// Thread grid 16x16: each thread owns 8 score rows x 4 cols, 8x4 of O.
// Smem: Qs[128][64], Ks[64(d)][64(key)] (transposed), Vs[64][64], Ps[128][64].
// ---------------------------------------------------------------------------
__global__ __launch_bounds__(256, 2) void attn_kernel()
{
    extern __shared__ float sm[];
    float* Qs = sm;                       // 128*64
    float* Ks = Qs + 128 * 64;            // 64*64  [dd][key]
    float* Vs = Ks + 64 * 64;             // 64*64  [key][dd]
    float* Ps = Vs + 64 * 64;             // 128*64 [row][key]

    const int bh = blockIdx.y;
    const int q0 = blockIdx.x * 128;
    const float* Qg = g_Q + (size_t)bh * NT * ND;
    const float* Kg = g_K + (size_t)bh * NT * ND;
    const float* Vg = g_V + (size_t)bh * NT * ND;

    const int tid = threadIdx.x;
    const int ty = tid >> 4, tx = tid & 15;
    const float scale = 0.125f;           // 1/sqrt(64)

    // Load Q tile, pre-scaled (visibility covered by first in-loop sync).
#pragma unroll
    for (int i = 0; i < 8; i++) {
        int lin = tid + i * 256;          // 0..2047
        int row = lin >> 4;
        int c4  = (lin & 15) * 4;
        float4 v = *(const float4*)(Qg + (size_t)(q0 + row) * ND + c4);
        v.x *= scale; v.y *= scale; v.z *= scale; v.w *= scale;
        *(float4*)(Qs + row * 64 + c4) = v;
    }

    float m_i[8], l_i[8], O[8][4];
#pragma unroll
    for (int i = 0; i < 8; i++) {
        m_i[i] = -1e30f; l_i[i] = 0.f;
#pragma unroll
        for (int j = 0; j < 4; j++) O[i][j] = 0.f;
    }

    for (int kb = 0; kb < NT / 64; kb++) {
        const int k0 = kb * 64;
        // Load K (transposed to [dd][key]) and V ([key][dd]).
#pragma unroll
        for (int i = 0; i < 4; i++) {
            int lin = tid + i * 256;      // 0..1023
            int key = lin >> 4;
            int c4  = (lin & 15) * 4;
            float4 kv = *(const float4*)(Kg + (size_t)(k0 + key) * ND + c4);
            Ks[(c4 + 0) * 64 + key] = kv.x;
            Ks[(c4 + 1) * 64 + key] = kv.y;
            Ks[(c4 + 2) * 64 + key] = kv.z;
            Ks[(c4 + 3) * 64 + key] = kv.w;
            float4 vv = *(const float4*)(Vg + (size_t)(k0 + key) * ND + c4);
            *(float4*)(Vs + key * 64 + c4) = vv;
        }
        __syncthreads();

        // S = Qs @ Ks  (already scaled)
        float s[8][4];
#pragma unroll
        for (int i = 0; i < 8; i++)
#pragma unroll
            for (int j = 0; j < 4; j++) s[i][j] = 0.f;
#pragma unroll 8
        for (int dd = 0; dd < 64; dd++) {
            float a[8];
#pragma unroll
            for (int i = 0; i < 8; i++) a[i] = Qs[(ty * 8 + i) * 64 + dd];
            float bq[4];
            *(float4*)bq = *(const float4*)(Ks + dd * 64 + tx * 4);
#pragma unroll
            for (int i = 0; i < 8; i++)
#pragma unroll
                for (int j = 0; j < 4; j++) s[i][j] += a[i] * bq[j];
        }

        // Online softmax. 16-lane butterfly: lanes with the same ty occupy a
        // contiguous 16-lane half (lane = (ty&1)*16 + tx), so xor 1..8 stays
        // within the row group.
#pragma unroll
        for (int i = 0; i < 8; i++) {
            float mt = fmaxf(fmaxf(s[i][0], s[i][1]), fmaxf(s[i][2], s[i][3]));
#pragma unroll
            for (int off = 1; off < 16; off <<= 1)
                mt = fmaxf(mt, __shfl_xor_sync(0xffffffffu, mt, off));
            float mn = fmaxf(m_i[i], mt);
            float alpha = __expf(m_i[i] - mn);
            m_i[i] = mn;
            float rs = 0.f;
#pragma unroll
            for (int j = 0; j < 4; j++) {
                float p = __expf(s[i][j] - mn);
                s[i][j] = p;
                rs += p;
            }
#pragma unroll
            for (int off = 1; off < 16; off <<= 1)
                rs += __shfl_xor_sync(0xffffffffu, rs, off);
            l_i[i] = l_i[i] * alpha + rs;
#pragma unroll
            for (int j = 0; j < 4; j++) O[i][j] *= alpha;
            *(float4*)(Ps + (ty * 8 + i) * 64 + tx * 4) = *(float4*)&s[i][0];
        }
        __syncthreads();

        // O += P @ V
#pragma unroll 8
        for (int kk = 0; kk < 64; kk++) {
            float p[8];
#pragma unroll
            for (int i = 0; i < 8; i++) p[i] = Ps[(ty * 8 + i) * 64 + kk];
            float v4[4];
            *(float4*)v4 = *(const float4*)(Vs + kk * 64 + tx * 4);
#pragma unroll
            for (int i = 0; i < 8; i++)
#pragma unroll
                for (int j = 0; j < 4; j++) O[i][j] += p[i] * v4[j];
        }
        __syncthreads();
    }

    // Epilogue: normalize and write into [B,T,C] layout for the proj GEMM.
    const int b = bh >> 4, h = bh & 15;
#pragma unroll
    for (int i = 0; i < 8; i++) {
        float inv = 1.0f / l_i[i];
        int t = q0 + ty * 8 + i;
        float4 o = make_float4(O[i][0] * inv, O[i][1] * inv,
                               O[i][2] * inv, O[i][3] * inv);
        *(float4*)(g_Y + (size_t)(b * NT + t) * NC + h * 64 + tx * 4) = o;
    }
}

// ---------------------------------------------------------------------------
// Kernel 3: out = Y @ W_proj^T + b_proj.  A = g_Y [4096,1024], B [1024,1024].
// ---------------------------------------------------------------------------
__global__ __launch_bounds__(256) void proj_gemm_kernel(
    const float* __restrict__ B, const float* __restrict__ bias,
    float* __restrict__ out)
{
    __shared__ float As[16][128];
    __shared__ float Bs[16][128];
    const int m0 = blockIdx.y * 128;
    const int n0 = blockIdx.x * 128;
    const int tid = threadIdx.x;
    const int ty = tid >> 4, tx = tid & 15;
    const float* A = g_Y;

    float acc[8][8];
#pragma unroll
    for (int i = 0; i < 8; i++)
#pragma unroll
        for (int j = 0; j < 8; j++) acc[i][j] = 0.f;

    for (int kt = 0; kt < NC; kt += 16) {
#pragma unroll
        for (int i = 0; i < 2; i++) {
            int lin = tid + i * 256;
            int row = lin >> 2;
            int k4  = (lin & 3) * 4;
            float4 av = *(const float4*)(A + (size_t)(m0 + row) * NC + kt + k4);
            As[k4+0][row] = av.x; As[k4+1][row] = av.y;
            As[k4+2][row] = av.z; As[k4+3][row] = av.w;
            float4 bv = *(const float4*)(B + (size_t)(n0 + row) * NC + kt + k4);
            Bs[k4+0][row] = bv.x; Bs[k4+1][row] = bv.y;
            Bs[k4+2][row] = bv.z; Bs[k4+3][row] = bv.w;
        }
        __syncthreads();
#pragma unroll 8
        for (int kk = 0; kk < 16; kk++) {
            float a[8], b[8];
            *(float4*)&a[0] = *(const float4*)&As[kk][ty * 8];
            *(float4*)&a[4] = *(const float4*)&As[kk][ty * 8 + 4];
            *(float4*)&b[0] = *(const float4*)&Bs[kk][tx * 8];
            *(float4*)&b[4] = *(const float4*)&Bs[kk][tx * 8 + 4];
#pragma unroll
            for (int i = 0; i < 8; i++)
#pragma unroll
                for (int j = 0; j < 8; j++) acc[i][j] += a[i] * b[j];
        }
        __syncthreads();
    }

    const int n = n0 + tx * 8;
    float4 bb0 = *(const float4*)(bias + n);
    float4 bb1 = *(const float4*)(bias + n + 4);
#pragma unroll
    for (int i = 0; i < 8; i++) {
        int m = m0 + ty * 8 + i;
        float4 o0 = make_float4(acc[i][0] + bb0.x, acc[i][1] + bb0.y,
                                acc[i][2] + bb0.z, acc[i][3] + bb0.w);
        float4 o1 = make_float4(acc[i][4] + bb1.x, acc[i][5] + bb1.y,
                                acc[i][6] + bb1.z, acc[i][7] + bb1.w);
        *(float4*)(out + (size_t)m * NC + n)     = o0;
        *(float4*)(out + (size_t)m * NC + n + 4) = o1;
    }
}

// ---------------------------------------------------------------------------
extern "C" void kernel_launch(void* const* d_in, const int* in_sizes, int n_in,
                              void* d_out, int out_size)
{
    const float* x      = (const float*)d_in[0];
    const float* W_attn = (const float*)d_in[1];
    const float* W_proj = (const float*)d_in[2];
    const float* b_proj = (const float*)d_in[3];
    float* out = (float*)d_out;

    // 1) QKV projection + scatter to [B,H,T,d]
    qkv_gemm_kernel<<<dim3(3 * NC / 128, MTOT / 128), 256>>>(x, W_attn);

    // 2) Flash attention (96 KB dynamic smem)
    size_t smem = (size_t)(128 * 64 + 64 * 64 + 64 * 64 + 128 * 64) * sizeof(float);
    cudaFuncSetAttribute(attn_kernel,
                         cudaFuncAttributeMaxDynamicSharedMemorySize, (int)smem);
    attn_kernel<<<dim3(NT / 128, NB * NH), 256, smem>>>();

    // 3) Output projection + bias
    proj_gemm_kernel<<<dim3(NC / 128, MTOT / 128), 256>>>(W_proj, b_proj, out);
}